// round 14
// baseline (speedup 1.0000x reference)
#include <cuda_runtime.h>
#include <cuda_fp16.h>
#include <cstdint>

// out = concat(adj_t @ x, adj_t2 @ x), N=8192, D=256, fp32.
// R14: R13 + A converted to fp16 EN ROUTE to smem (LDG.128 -> cvt.f16x2 ->
// STS.128, register-staged one iteration ahead). Crossbar bytes drop below
// the HMMA issue floor, making the tensor pipe the sole binder.

constexpr int NN = 8192;
constexpr int DD = 256;
constexpr int BM = 64;
constexpr int BK = 64;
constexpr int NITER = NN / BK;            // 128
constexpr int ASH = 72;                   // halves per A row (64 + 8 pad)
constexpr int A_BYTES = BM * ASH * 2;     // 9216 B per matrix
constexpr int BSH = 72;                   // halves per B row (g_xh transposed)
constexpr int B_OFF = 2 * A_BYTES;        // 18432
constexpr int STG_BYTES = B_OFF + DD * BSH * 2;   // 18432 + 36864 = 55296
constexpr int SMEM_BYTES = 2 * STG_BYTES;         // 110592

__device__ __half g_xh[(size_t)DD * NN];  // x transposed [n][k], fp16 rn

#define CP_ASYNC16(dst, src) \
    asm volatile("cp.async.cg.shared.global [%0], [%1], 16;" :: "r"(dst), "l"(src))

__device__ __forceinline__ uint32_t smem_u32(const void* p) {
    uint32_t a;
    asm("{ .reg .u64 t; cvta.to.shared.u64 t, %1; cvt.u32.u64 %0, t; }"
        : "=r"(a) : "l"(p));
    return a;
}

__device__ __forceinline__ uint32_t pack_h2(float lo, float hi) {
    uint32_t r;   // cvt.rn.f16x2.f32 d, hi, lo -> lo lands in low half
    asm("cvt.rn.f16x2.f32 %0, %1, %2;" : "=r"(r) : "f"(hi), "f"(lo));
    return r;
}

__device__ __forceinline__ void mma_f16(float c[4], const uint32_t a[4],
                                        const uint32_t b0, const uint32_t b1) {
    asm volatile(
        "mma.sync.aligned.m16n8k16.row.col.f32.f16.f16.f32 "
        "{%0,%1,%2,%3}, {%4,%5,%6,%7}, {%8,%9}, {%0,%1,%2,%3};"
        : "+f"(c[0]), "+f"(c[1]), "+f"(c[2]), "+f"(c[3])
        : "r"(a[0]), "r"(a[1]), "r"(a[2]), "r"(a[3]), "r"(b0), "r"(b1));
}

// ---------------- prep: x -> fp16(rn), transposed to [DD][NN] ----------------
__global__ void xprep(const float* __restrict__ x) {
    __shared__ float tile[32][33];
    const int kb = blockIdx.x * 32;
    const int nb = blockIdx.y * 32;
    const int tx = threadIdx.x;
    const int ty = threadIdx.y;   // blockDim (32, 8)
#pragma unroll
    for (int j = 0; j < 32; j += 8)
        tile[ty + j][tx] = x[(size_t)(kb + ty + j) * DD + nb + tx];
    __syncthreads();
#pragma unroll
    for (int j = 0; j < 32; j += 8)
        g_xh[(size_t)(nb + ty + j) * NN + kb + tx] = __float2half_rn(tile[tx][ty + j]);
}

// ---------------- fused GEMM, all-fp16 smem ----------------
__global__ void __launch_bounds__(256, 1) h2gcn_mma(
    const float* __restrict__ adj1,
    const float* __restrict__ adj2,
    float* __restrict__ out)
{
    extern __shared__ char smc[];
    const uint32_t smb = smem_u32(smc);

    const int t    = threadIdx.x;
    const int wid  = t >> 5;
    const int lane = t & 31;
    const int m0   = blockIdx.x * BM;

    const int wm  = wid & 1;         // 2 warp rows (32 M each)
    const int wn  = wid >> 1;        // 4 warp cols (64 N each)
    const int gid = lane >> 2;
    const int tig = lane & 3;
    const int koff = (wid >> 2) * 2; // SMSP buddy anti-phase

    // ---- A staging assignment: per matrix, thread t -> row t>>2, 16-half
    // chunk q=t&3 (halves [16q,16q+16) = floats [16q,16q+16) of the BK window)
    const int arow = t >> 2;
    const int aq   = t & 3;
    const float* a1g = adj1 + (size_t)(m0 + arow) * NN + aq * 16;
    const float* a2g = adj2 + (size_t)(m0 + arow) * NN + aq * 16;
    const uint32_t asts = (uint32_t)(arow * (ASH * 2) + aq * 32);  // byte off in A region

    // ---- B cp.async assignment (same as R13) ----
    const char* bp[8]; uint32_t bdst[8];
#pragma unroll
    for (int j = 0; j < 8; j++) {
        int id = t + 256 * j;
        int n  = id >> 3;             // 0..255
        int c  = id & 7;              // 16B chunk within 64-half row
        bp[j] = reinterpret_cast<const char*>(g_xh + (size_t)n * NN) + c * 16;
        bdst[j] = (uint32_t)(B_OFF + n * (BSH * 2) + c * 16);
    }

    auto load_B = [&](int buf) {
        const uint32_t sb = smb + (uint32_t)(buf * STG_BYTES);
#pragma unroll
        for (int j = 0; j < 8; j++) {
            CP_ASYNC16(sb + bdst[j], bp[j]);
            bp[j] += BK * 2;          // 64 halves forward in k
        }
        asm volatile("cp.async.commit_group;");
    };

    float4 a1s[4], a2s[4];            // A staging regs (16 floats per matrix)
    auto ldg_A = [&]() {
#pragma unroll
        for (int j = 0; j < 4; j++) {
            a1s[j] = *reinterpret_cast<const float4*>(a1g + 4 * j);
            a2s[j] = *reinterpret_cast<const float4*>(a2g + 4 * j);
        }
        a1g += BK; a2g += BK;
    };
    auto sts_A = [&](int buf) {
        const uint32_t sb = smb + (uint32_t)(buf * STG_BYTES);
        uint4 lo, hi;
        lo.x = pack_h2(a1s[0].x, a1s[0].y); lo.y = pack_h2(a1s[0].z, a1s[0].w);
        lo.z = pack_h2(a1s[1].x, a1s[1].y); lo.w = pack_h2(a1s[1].z, a1s[1].w);
        hi.x = pack_h2(a1s[2].x, a1s[2].y); hi.y = pack_h2(a1s[2].z, a1s[2].w);
        hi.z = pack_h2(a1s[3].x, a1s[3].y); hi.w = pack_h2(a1s[3].z, a1s[3].w);
        *reinterpret_cast<uint4*>(smc + (sb - smb) + asts)      = lo;
        *reinterpret_cast<uint4*>(smc + (sb - smb) + asts + 16) = hi;
        lo.x = pack_h2(a2s[0].x, a2s[0].y); lo.y = pack_h2(a2s[0].z, a2s[0].w);
        lo.z = pack_h2(a2s[1].x, a2s[1].y); lo.w = pack_h2(a2s[1].z, a2s[1].w);
        hi.x = pack_h2(a2s[2].x, a2s[2].y); hi.y = pack_h2(a2s[2].z, a2s[2].w);
        hi.z = pack_h2(a2s[3].x, a2s[3].y); hi.w = pack_h2(a2s[3].z, a2s[3].w);
        *reinterpret_cast<uint4*>(smc + (sb - smb) + A_BYTES + asts)      = lo;
        *reinterpret_cast<uint4*>(smc + (sb - smb) + A_BYTES + asts + 16) = hi;
    };

    float acc[2][2][8][4];
#pragma unroll
    for (int g = 0; g < 2; g++)
#pragma unroll
        for (int mt = 0; mt < 2; mt++)
#pragma unroll
            for (int nt = 0; nt < 8; nt++)
#pragma unroll
                for (int i = 0; i < 4; i++) acc[g][mt][nt][i] = 0.0f;

    // Prologue: A(0) via LDG->cvt->STS into buf0; B(0) via cp.async into buf0
    ldg_A();
    load_B(0);
    sts_A(0);

    for (int it = 0; it < NITER; it++) {
        asm volatile("cp.async.wait_group 0;");   // B(it) complete
        __syncthreads();                           // A(it) STS + B(it) visible

        const int buf = it & 1;
        if (it + 1 < NITER) {
            ldg_A();                 // A(it+1) -> regs (latency under compute)
            load_B(buf ^ 1);         // B(it+1) -> other buffer
        }

        const char* stage = smc + buf * STG_BYTES;
        const __half* sA1 = reinterpret_cast<const __half*>(stage);
        const __half* sA2 = reinterpret_cast<const __half*>(stage + A_BYTES);
        const __half* sB  = reinterpret_cast<const __half*>(stage + B_OFF);

        const int abase = (wm * 32 + gid) * ASH + 2 * tig;
        const int bn0   = wn * 64 + gid;

#pragma unroll
        for (int ks = 0; ks < 4; ks++) {
            const int k0 = ((ks + koff) & 3) * 16;
            uint32_t b0[8], b1[8];
#pragma unroll
            for (int nt = 0; nt < 8; nt++) {
                const __half* pb = sB + (size_t)(bn0 + nt * 8) * BSH + k0 + 2 * tig;
                b0[nt] = *reinterpret_cast<const uint32_t*>(pb);
                b1[nt] = *reinterpret_cast<const uint32_t*>(pb + 8);
            }
            uint32_t a[2][2][4];
#pragma unroll
            for (int g = 0; g < 2; g++) {
                const __half* sA = g ? sA2 : sA1;
#pragma unroll
                for (int mt = 0; mt < 2; mt++) {
                    const __half* pa = sA + abase + mt * 16 * ASH + k0;
                    a[g][mt][0] = *reinterpret_cast<const uint32_t*>(pa);
                    a[g][mt][1] = *reinterpret_cast<const uint32_t*>(pa + 8 * ASH);
                    a[g][mt][2] = *reinterpret_cast<const uint32_t*>(pa + 8);
                    a[g][mt][3] = *reinterpret_cast<const uint32_t*>(pa + 8 * ASH + 8);
                }
            }
#pragma unroll
            for (int g = 0; g < 2; g++)
#pragma unroll
                for (int mt = 0; mt < 2; mt++)
#pragma unroll
                    for (int nt = 0; nt < 8; nt++)
                        mma_f16(acc[g][mt][nt], a[g][mt], b0[nt], b1[nt]);
        }

        // Convert + store A(it+1) into the other buffer (made visible by the
        // __syncthreads at the top of the next iteration).
        if (it + 1 < NITER) sts_A(buf ^ 1);
    }

    // Epilogue: out[8192, 512]; matrix g at column offset g*256
#pragma unroll
    for (int g = 0; g < 2; g++) {
        const int colbase = g * DD + wn * 64 + 2 * tig;
#pragma unroll
        for (int mt = 0; mt < 2; mt++) {
            const int row = m0 + wm * 32 + mt * 16 + gid;
#pragma unroll
            for (int nt = 0; nt < 8; nt++) {
                float* p0 = out + (size_t)row * (2 * DD) + colbase + nt * 8;
                float* p1 = p0 + 8 * (2 * DD);
                *reinterpret_cast<float2*>(p0) = make_float2(acc[g][mt][nt][0], acc[g][mt][nt][1]);
                *reinterpret_cast<float2*>(p1) = make_float2(acc[g][mt][nt][2], acc[g][mt][nt][3]);
            }
        }
    }
}

extern "C" void kernel_launch(void* const* d_in, const int* in_sizes, int n_in,
                              void* d_out, int out_size) {
    const float* x  = nullptr;
    const float* a1 = nullptr;
    const float* a2 = nullptr;
    for (int i = 0; i < n_in; i++) {
        if (in_sizes[i] == NN * DD)  x  = (const float*)d_in[i];
        else if (!a1)                a1 = (const float*)d_in[i];
        else                         a2 = (const float*)d_in[i];
    }

    static bool attr_set = false;
    if (!attr_set) {
        cudaFuncSetAttribute(h2gcn_mma,
                             cudaFuncAttributeMaxDynamicSharedMemorySize, SMEM_BYTES);
        attr_set = true;
    }

    xprep<<<dim3(NN / 32, DD / 32), dim3(32, 8)>>>(x);
    h2gcn_mma<<<NN / BM, 256, SMEM_BYTES>>>(a1, a2, (float*)d_out);
}

// round 15
// speedup vs baseline: 1.0175x; 1.0175x over previous
#include <cuda_runtime.h>
#include <cuda_fp16.h>
#include <cstdint>

// out = concat(adj_t @ x, adj_t2 @ x), N=8192, D=256, fp32.
// R15: R14 (A converted fp32->fp16 en route to smem) with staging register
// pressure halved: A1 and A2 are LDG'd/converted/STS'd SEQUENTIALLY through
// one 16-reg buffer, interleaved between ks compute phases. Crossbar bytes
// (~176 KB/iter) sit below the HMMA issue floor -> tensor-bound target.

constexpr int NN = 8192;
constexpr int DD = 256;
constexpr int BM = 64;
constexpr int BK = 64;
constexpr int NITER = NN / BK;            // 128
constexpr int ASH = 72;                   // halves per A row (64 + 8 pad)
constexpr int A_BYTES = BM * ASH * 2;     // 9216 B per matrix
constexpr int BSH = 72;                   // halves per B row (g_xh transposed)
constexpr int B_OFF = 2 * A_BYTES;        // 18432
constexpr int STG_BYTES = B_OFF + DD * BSH * 2;   // 55296
constexpr int SMEM_BYTES = 2 * STG_BYTES;         // 110592

__device__ __half g_xh[(size_t)DD * NN];  // x transposed [n][k], fp16 rn

#define CP_ASYNC16(dst, src) \
    asm volatile("cp.async.cg.shared.global [%0], [%1], 16;" :: "r"(dst), "l"(src))

__device__ __forceinline__ uint32_t smem_u32(const void* p) {
    uint32_t a;
    asm("{ .reg .u64 t; cvta.to.shared.u64 t, %1; cvt.u32.u64 %0, t; }"
        : "=r"(a) : "l"(p));
    return a;
}

__device__ __forceinline__ uint32_t pack_h2(float lo, float hi) {
    uint32_t r;
    asm("cvt.rn.f16x2.f32 %0, %1, %2;" : "=r"(r) : "f"(hi), "f"(lo));
    return r;
}

__device__ __forceinline__ void mma_f16(float c[4], const uint32_t a[4],
                                        const uint32_t b0, const uint32_t b1) {
    asm volatile(
        "mma.sync.aligned.m16n8k16.row.col.f32.f16.f16.f32 "
        "{%0,%1,%2,%3}, {%4,%5,%6,%7}, {%8,%9}, {%0,%1,%2,%3};"
        : "+f"(c[0]), "+f"(c[1]), "+f"(c[2]), "+f"(c[3])
        : "r"(a[0]), "r"(a[1]), "r"(a[2]), "r"(a[3]), "r"(b0), "r"(b1));
}

// ---------------- prep: x -> fp16(rn), transposed to [DD][NN] ----------------
__global__ void xprep(const float* __restrict__ x) {
    __shared__ float tile[32][33];
    const int kb = blockIdx.x * 32;
    const int nb = blockIdx.y * 32;
    const int tx = threadIdx.x;
    const int ty = threadIdx.y;   // blockDim (32, 8)
#pragma unroll
    for (int j = 0; j < 32; j += 8)
        tile[ty + j][tx] = x[(size_t)(kb + ty + j) * DD + nb + tx];
    __syncthreads();
#pragma unroll
    for (int j = 0; j < 32; j += 8)
        g_xh[(size_t)(nb + ty + j) * NN + kb + tx] = __float2half_rn(tile[tx][ty + j]);
}

// ---------------- fused GEMM, all-fp16 smem ----------------
__global__ void __launch_bounds__(256, 1) h2gcn_mma(
    const float* __restrict__ adj1,
    const float* __restrict__ adj2,
    float* __restrict__ out)
{
    extern __shared__ char smc[];
    const uint32_t smb = smem_u32(smc);

    const int t    = threadIdx.x;
    const int wid  = t >> 5;
    const int lane = t & 31;
    const int m0   = blockIdx.x * BM;

    const int wm  = wid & 1;         // 2 warp rows (32 M each)
    const int wn  = wid >> 1;        // 4 warp cols (64 N each)
    const int gid = lane >> 2;
    const int tig = lane & 3;
    const int koff = (wid >> 2) * 2; // SMSP buddy anti-phase

    // ---- A staging assignment: thread t -> row t>>2, 16-float chunk q=t&3
    const int arow = t >> 2;
    const int aq   = t & 3;
    const float* a1g = adj1 + (size_t)(m0 + arow) * NN + aq * 16;
    const float* a2g = adj2 + (size_t)(m0 + arow) * NN + aq * 16;
    const uint32_t asts = (uint32_t)(arow * (ASH * 2) + aq * 32);  // bytes in A region

    // ---- B cp.async assignment ----
    const char* bp[8]; uint32_t bdst[8];
#pragma unroll
    for (int j = 0; j < 8; j++) {
        int id = t + 256 * j;
        int n  = id >> 3;             // 0..255
        int c  = id & 7;              // 16B chunk within 64-half row
        bp[j] = reinterpret_cast<const char*>(g_xh + (size_t)n * NN) + c * 16;
        bdst[j] = (uint32_t)(B_OFF + n * (BSH * 2) + c * 16);
    }

    auto load_B = [&](int buf) {
        const uint32_t sb = smb + (uint32_t)(buf * STG_BYTES);
#pragma unroll
        for (int j = 0; j < 8; j++) {
            CP_ASYNC16(sb + bdst[j], bp[j]);
            bp[j] += BK * 2;
        }
        asm volatile("cp.async.commit_group;");
    };

    // One 16-reg staging buffer, reused for A1 then A2.
    float4 as[4];
    auto ldgA = [&](const float*& gp) {
#pragma unroll
        for (int j = 0; j < 4; j++)
            as[j] = *reinterpret_cast<const float4*>(gp + 4 * j);
        gp += BK;
    };
    auto stsA = [&](int buf, int matoff) {
        uint4 lo, hi;
        lo.x = pack_h2(as[0].x, as[0].y); lo.y = pack_h2(as[0].z, as[0].w);
        lo.z = pack_h2(as[1].x, as[1].y); lo.w = pack_h2(as[1].z, as[1].w);
        hi.x = pack_h2(as[2].x, as[2].y); hi.y = pack_h2(as[2].z, as[2].w);
        hi.z = pack_h2(as[3].x, as[3].y); hi.w = pack_h2(as[3].z, as[3].w);
        char* base = smc + buf * STG_BYTES + matoff + asts;
        *reinterpret_cast<uint4*>(base)      = lo;
        *reinterpret_cast<uint4*>(base + 16) = hi;
    };

    float acc[2][2][8][4];
#pragma unroll
    for (int g = 0; g < 2; g++)
#pragma unroll
        for (int mt = 0; mt < 2; mt++)
#pragma unroll
            for (int nt = 0; nt < 8; nt++)
#pragma unroll
                for (int i = 0; i < 4; i++) acc[g][mt][nt][i] = 0.0f;

    const int abase = (wm * 32 + gid) * ASH + 2 * tig;
    const int bn0   = wn * 64 + gid;

    // Prologue: A(0) through the single staging buffer; B(0) via cp.async.
    load_B(0);
    ldgA(a1g); stsA(0, 0);
    ldgA(a2g); stsA(0, A_BYTES);

    for (int it = 0; it < NITER; it++) {
        asm volatile("cp.async.wait_group 0;");   // B(it) complete
        __syncthreads();                           // A(it) + B(it) visible

        const int buf  = it & 1;
        const int nbuf = buf ^ 1;
        const bool more = (it + 1 < NITER);

        if (more) {
            load_B(nbuf);
            ldgA(a1g);               // A1(it+1) -> regs; lands during ks0/ks1
        }

        const char* stage = smc + buf * STG_BYTES;
        const __half* sA1 = reinterpret_cast<const __half*>(stage);
        const __half* sA2 = reinterpret_cast<const __half*>(stage + A_BYTES);
        const __half* sB  = reinterpret_cast<const __half*>(stage + B_OFF);

        // one ks compute phase
        auto phase = [&](int ks) {
            const int k0 = ((ks + koff) & 3) * 16;
            uint32_t b0[8], b1[8];
#pragma unroll
            for (int nt = 0; nt < 8; nt++) {
                const __half* pb = sB + (size_t)(bn0 + nt * 8) * BSH + k0 + 2 * tig;
                b0[nt] = *reinterpret_cast<const uint32_t*>(pb);
                b1[nt] = *reinterpret_cast<const uint32_t*>(pb + 8);
            }
            uint32_t a[2][2][4];
#pragma unroll
            for (int g = 0; g < 2; g++) {
                const __half* sA = g ? sA2 : sA1;
#pragma unroll
                for (int mt = 0; mt < 2; mt++) {
                    const __half* pa = sA + abase + mt * 16 * ASH + k0;
                    a[g][mt][0] = *reinterpret_cast<const uint32_t*>(pa);
                    a[g][mt][1] = *reinterpret_cast<const uint32_t*>(pa + 8 * ASH);
                    a[g][mt][2] = *reinterpret_cast<const uint32_t*>(pa + 8);
                    a[g][mt][3] = *reinterpret_cast<const uint32_t*>(pa + 8 * ASH + 8);
                }
            }
#pragma unroll
            for (int g = 0; g < 2; g++)
#pragma unroll
                for (int mt = 0; mt < 2; mt++)
#pragma unroll
                    for (int nt = 0; nt < 8; nt++)
                        mma_f16(acc[g][mt][nt], a[g][mt], b0[nt], b1[nt]);
        };

        phase(0);
        phase(1);
        if (more) {
            stsA(nbuf, 0);           // A1(it+1) -> smem (LDG had ~2 phases)
            ldgA(a2g);               // A2(it+1) -> regs (same 16 regs)
        }
        phase(2);
        phase(3);
        if (more) stsA(nbuf, A_BYTES);   // A2(it+1) -> smem
    }

    // Epilogue: out[8192, 512]; matrix g at column offset g*256
#pragma unroll
    for (int g = 0; g < 2; g++) {
        const int colbase = g * DD + wn * 64 + 2 * tig;
#pragma unroll
        for (int mt = 0; mt < 2; mt++) {
            const int row = m0 + wm * 32 + mt * 16 + gid;
#pragma unroll
            for (int nt = 0; nt < 8; nt++) {
                float* p0 = out + (size_t)row * (2 * DD) + colbase + nt * 8;
                float* p1 = p0 + 8 * (2 * DD);
                *reinterpret_cast<float2*>(p0) = make_float2(acc[g][mt][nt][0], acc[g][mt][nt][1]);
                *reinterpret_cast<float2*>(p1) = make_float2(acc[g][mt][nt][2], acc[g][mt][nt][3]);
            }
        }
    }
}

extern "C" void kernel_launch(void* const* d_in, const int* in_sizes, int n_in,
                              void* d_out, int out_size) {
    const float* x  = nullptr;
    const float* a1 = nullptr;
    const float* a2 = nullptr;
    for (int i = 0; i < n_in; i++) {
        if (in_sizes[i] == NN * DD)  x  = (const float*)d_in[i];
        else if (!a1)                a1 = (const float*)d_in[i];
        else                         a2 = (const float*)d_in[i];
    }

    static bool attr_set = false;
    if (!attr_set) {
        cudaFuncSetAttribute(h2gcn_mma,
                             cudaFuncAttributeMaxDynamicSharedMemorySize, SMEM_BYTES);
        attr_set = true;
    }

    xprep<<<dim3(NN / 32, DD / 32), dim3(32, 8)>>>(x);
    h2gcn_mma<<<NN / BM, 256, SMEM_BYTES>>>(a1, a2, (float*)d_out);
}

// round 16
// speedup vs baseline: 1.1457x; 1.1260x over previous
#include <cuda_runtime.h>
#include <cuda_fp16.h>
#include <cstdint>

// out = concat(adj_t @ x, adj_t2 @ x), N=8192, D=256, fp32.
// R16: two INDEPENDENT 128-thread pipelines in one CTA (named barriers,
// disjoint smem, one matrix each) seeded into anti-phase so one group's
// LDS burst overlaps the other group's MMA burst. Arithmetic == R13.

constexpr int NN = 8192;
constexpr int DD = 256;
constexpr int BM = 64;
constexpr int BK = 64;
constexpr int NITER = NN / BK;            // 128
constexpr int ASTRIDE = 72;               // A row stride in floats (CF LDS.64)
constexpr int BSH = 72;                   // B row stride in halves (CF LDS.32)
constexpr int A_ST = BM * ASTRIDE * 4;    // 18432 B per stage
constexpr int B_ST = DD * BSH * 2;        // 36864 B per stage (256 n rows)
constexpr int B_OFF = A_ST;               // B after A within a stage
constexpr int STG = A_ST + B_ST;          // 55296
constexpr int GRP_BYTES = 2 * STG;        // 110592 per group (2 stages)
constexpr int SMEM_BYTES = 2 * GRP_BYTES; // 221184

__device__ __half g_xh[(size_t)DD * NN];  // x transposed [n][k], fp16 rn

#define CP_ASYNC16(dst, src) \
    asm volatile("cp.async.cg.shared.global [%0], [%1], 16;" :: "r"(dst), "l"(src))

__device__ __forceinline__ uint32_t smem_u32(const void* p) {
    uint32_t a;
    asm("{ .reg .u64 t; cvta.to.shared.u64 t, %1; cvt.u32.u64 %0, t; }"
        : "=r"(a) : "l"(p));
    return a;
}

__device__ __forceinline__ uint32_t pack_h2(float lo, float hi) {
    uint32_t r;
    asm("cvt.rn.f16x2.f32 %0, %1, %2;" : "=r"(r) : "f"(hi), "f"(lo));
    return r;
}

__device__ __forceinline__ void mma_f16(float c[4], const uint32_t a[4],
                                        const uint32_t b0, const uint32_t b1) {
    asm volatile(
        "mma.sync.aligned.m16n8k16.row.col.f32.f16.f16.f32 "
        "{%0,%1,%2,%3}, {%4,%5,%6,%7}, {%8,%9}, {%0,%1,%2,%3};"
        : "+f"(c[0]), "+f"(c[1]), "+f"(c[2]), "+f"(c[3])
        : "r"(a[0]), "r"(a[1]), "r"(a[2]), "r"(a[3]), "r"(b0), "r"(b1));
}

// ---------------- prep: x -> fp16(rn), transposed to [DD][NN] ----------------
__global__ void xprep(const float* __restrict__ x) {
    __shared__ float tile[32][33];
    const int kb = blockIdx.x * 32;
    const int nb = blockIdx.y * 32;
    const int tx = threadIdx.x;
    const int ty = threadIdx.y;   // blockDim (32, 8)
#pragma unroll
    for (int j = 0; j < 32; j += 8)
        tile[ty + j][tx] = x[(size_t)(kb + ty + j) * DD + nb + tx];
    __syncthreads();
#pragma unroll
    for (int j = 0; j < 32; j += 8)
        g_xh[(size_t)(nb + ty + j) * NN + kb + tx] = __float2half_rn(tile[tx][ty + j]);
}

// ---------------- fused GEMM: two anti-phased groups ----------------
__global__ void __launch_bounds__(256, 1) h2gcn_mma(
    const float* __restrict__ adj1,
    const float* __restrict__ adj2,
    float* __restrict__ out)
{
    extern __shared__ char smc[];

    const int t    = threadIdx.x;
    const int wid  = t >> 5;
    const int lane = t & 31;
    const int m0   = blockIdx.x * BM;

    const int gsel = wid >> 2;        // group / matrix selector
    const int wn   = wid & 3;         // warp column within group (64 N each)
    const int t128 = t & 127;
    const int gid  = lane >> 2;
    const int tig  = lane & 3;

    const float* adj = gsel ? adj2 : adj1;
    const uint32_t gbase = smem_u32(smc) + (uint32_t)(gsel * GRP_BYTES);
    const char*    gptr  = smc + gsel * GRP_BYTES;

    // ---- cp.async bases (128 threads per group) ----
    // A: 64 rows x 16 chunks = 1024 -> 8/thread; chunk j: row += 8 per j
    //    (byte strides: gmem 8*NN*4 = 262144, smem 8*ASTRIDE*4 = 2304)
    // B: 256 n x 8 chunks = 2048 -> 16/thread; chunk j: n += 16 per j
    //    (byte strides: gmem 16*NN*2 = 262144, smem 16*BSH*2 = 2304)
    const char* agp = reinterpret_cast<const char*>(
        adj + (size_t)(m0 + (t128 >> 4)) * NN + (t128 & 15) * 4);
    const char* bgp = reinterpret_cast<const char*>(
        g_xh + (size_t)(t128 >> 3) * NN) + (t128 & 7) * 16;
    const uint32_t adst0 = (uint32_t)((t128 >> 4) * (ASTRIDE * 4) + (t128 & 15) * 16);
    const uint32_t bdst0 = (uint32_t)(B_OFF + (t128 >> 3) * (BSH * 2) + (t128 & 7) * 16);

    auto load_stage = [&](int buf) {
        const uint32_t sb = gbase + (uint32_t)(buf * STG);
#pragma unroll
        for (int j = 0; j < 8; j++)
            CP_ASYNC16(sb + adst0 + j * 2304, agp + (size_t)j * 262144);
#pragma unroll
        for (int j = 0; j < 16; j++)
            CP_ASYNC16(sb + bdst0 + j * 2304, bgp + (size_t)j * 262144);
        agp += BK * 4;    // advance K by 64 floats
        bgp += BK * 2;    // advance K by 64 halves
        asm volatile("cp.async.commit_group;");
    };

    float acc[4][8][4];   // warp tile 64M x 64N, one matrix
#pragma unroll
    for (int mt = 0; mt < 4; mt++)
#pragma unroll
        for (int nt = 0; nt < 8; nt++)
#pragma unroll
            for (int i = 0; i < 4; i++) acc[mt][nt][i] = 0.0f;

    const int abase = gid * ASTRIDE + 2 * tig;   // floats
    const int bn0   = wn * 64 + gid;

    load_stage(0);

    // Seed anti-phase: group 1 delays ~1200 cycles once.
    if (gsel) {
        unsigned long long s = clock64();
        while (clock64() - s < 1200ULL) { }
    }

    for (int it = 0; it < NITER; it++) {
        asm volatile("cp.async.wait_group 0;");
        asm volatile("bar.sync %0, 128;" :: "r"(gsel + 1) : "memory");

        const int buf = it & 1;
        if (it + 1 < NITER) load_stage(buf ^ 1);

        const char* stage = gptr + buf * STG;
        const float* sA = reinterpret_cast<const float*>(stage);
        const __half* sB = reinterpret_cast<const __half*>(stage + B_OFF);

#pragma unroll
        for (int ks = 0; ks < 4; ks++) {
            const int k0 = ks * 16;
            uint32_t b0[8], b1[8];
#pragma unroll
            for (int nt = 0; nt < 8; nt++) {
                const __half* pb = sB + (size_t)(bn0 + nt * 8) * BSH + k0 + 2 * tig;
                b0[nt] = *reinterpret_cast<const uint32_t*>(pb);
                b1[nt] = *reinterpret_cast<const uint32_t*>(pb + 8);
            }
            uint32_t a[4][4];
#pragma unroll
            for (int mt = 0; mt < 4; mt++) {
                const float* pa = sA + abase + mt * 16 * ASTRIDE + k0;
                float2 v0 = *reinterpret_cast<const float2*>(pa);
                float2 v1 = *reinterpret_cast<const float2*>(pa + 8 * ASTRIDE);
                float2 v2 = *reinterpret_cast<const float2*>(pa + 8);
                float2 v3 = *reinterpret_cast<const float2*>(pa + 8 * ASTRIDE + 8);
                a[mt][0] = pack_h2(v0.x, v0.y);
                a[mt][1] = pack_h2(v1.x, v1.y);
                a[mt][2] = pack_h2(v2.x, v2.y);
                a[mt][3] = pack_h2(v3.x, v3.y);
            }
#pragma unroll
            for (int mt = 0; mt < 4; mt++)
#pragma unroll
                for (int nt = 0; nt < 8; nt++)
                    mma_f16(acc[mt][nt], a[mt], b0[nt], b1[nt]);
        }
    }

    // Epilogue: out[8192, 512]; this group's matrix at column offset gsel*256
    const int colbase = gsel * DD + wn * 64 + 2 * tig;
#pragma unroll
    for (int mt = 0; mt < 4; mt++) {
        const int row = m0 + mt * 16 + gid;
#pragma unroll
        for (int nt = 0; nt < 8; nt++) {
            float* p0 = out + (size_t)row * (2 * DD) + colbase + nt * 8;
            float* p1 = p0 + 8 * (2 * DD);
            *reinterpret_cast<float2*>(p0) = make_float2(acc[mt][nt][0], acc[mt][nt][1]);
            *reinterpret_cast<float2*>(p1) = make_float2(acc[mt][nt][2], acc[mt][nt][3]);
        }
    }
}

extern "C" void kernel_launch(void* const* d_in, const int* in_sizes, int n_in,
                              void* d_out, int out_size) {
    const float* x  = nullptr;
    const float* a1 = nullptr;
    const float* a2 = nullptr;
    for (int i = 0; i < n_in; i++) {
        if (in_sizes[i] == NN * DD)  x  = (const float*)d_in[i];
        else if (!a1)                a1 = (const float*)d_in[i];
        else                         a2 = (const float*)d_in[i];
    }

    static bool attr_set = false;
    if (!attr_set) {
        cudaFuncSetAttribute(h2gcn_mma,
                             cudaFuncAttributeMaxDynamicSharedMemorySize, SMEM_BYTES);
        attr_set = true;
    }

    xprep<<<dim3(NN / 32, DD / 32), dim3(32, 8)>>>(x);
    h2gcn_mma<<<NN / BM, 256, SMEM_BYTES>>>(a1, a2, (float*)d_out);
}